// round 2
// baseline (speedup 1.0000x reference)
#include <cuda_runtime.h>

// ---------------------------------------------------------------------------
// KnowledgeMLP: fp32 baseline using packed fma.rn.f32x2 (2x FFMA throughput).
//
// Pipeline (all on default stream, graph-capturable, no allocations):
//   1) knowledge_kernel : knowledge[B,64] = sum_k mask * relu(kg[idx] @ Wkg + bkg)
//   2) gemm<512,128,R>  : h1 = relu(x @ W1a + b1a)
//   3) gemm<128,512,R>  : h2 = relu(h1 @ W1b + b1b)
//   4) gemm<512,128,R>  : h3 = relu(h2 @ W1c + b1c)
//   5) gemm<128, 64,R,+>: h4 = relu(h3 @ W1d + b1d) + knowledge
//   6) gemm< 64,1024>   : out = h4 @ W2 + b2
// ---------------------------------------------------------------------------

#define BB 8192
#define KK 50

// Scratch (device globals — no cudaMalloc allowed)
__device__ float g_h128a[BB * 128];
__device__ float g_h512 [BB * 512];
__device__ float g_h128b[BB * 128];
__device__ float g_h64  [BB * 64];
__device__ float g_know [BB * 64];

__device__ __forceinline__ void fma2(unsigned long long &d,
                                     unsigned long long a,
                                     unsigned long long b) {
    asm("fma.rn.f32x2 %0, %1, %2, %0;" : "+l"(d) : "l"(a), "l"(b));
}

__device__ __forceinline__ float unpack_sum(unsigned long long u) {
    float lo = __uint_as_float((unsigned)(u & 0xffffffffu));
    float hi = __uint_as_float((unsigned)(u >> 32));
    return lo + hi;
}

// ---------------------------------------------------------------------------
// Generic tiled GEMM: C[M,N] = act(A[M,KDIM] @ W[KDIM,N] + bias) (+ addsrc)
// Block tile 64x64, 256 threads, 4x4 per thread, K paired into f32x2 lanes.
// ---------------------------------------------------------------------------
#define TM 64
#define TN 64
#define TKC 32

template <int KDIM, int N, bool RELU, bool ADD>
__global__ __launch_bounds__(256) void gemm_kernel(
    const float* __restrict__ A, const float* __restrict__ W,
    const float* __restrict__ bias, const float* __restrict__ addsrc,
    float* __restrict__ C)
{
    __shared__ float As[TM][TKC];        // [row][k]
    __shared__ float Bs[TKC / 2][TN * 2];// [kpair][col*2 + parity]

    const int t  = threadIdx.x;
    const int tx = t & 15;
    const int ty = t >> 4;
    const int row0 = blockIdx.y * TM;
    const int col0 = blockIdx.x * TN;

    unsigned long long acc[4][4];
#pragma unroll
    for (int i = 0; i < 4; i++)
#pragma unroll
        for (int j = 0; j < 4; j++) acc[i][j] = 0ull;

    for (int k0 = 0; k0 < KDIM; k0 += TKC) {
        // Load A tile: 64x32 floats, float4 per thread x2
#pragma unroll
        for (int i = 0; i < 2; i++) {
            int f = t + i * 256;
            int r = f >> 3;
            int s = (f & 7) << 2;
            *(float4*)&As[r][s] =
                *(const float4*)&A[(size_t)(row0 + r) * KDIM + k0 + s];
        }
        // Load W tile into paired layout: Bs[k/2][c*2 + (k&1)] = W[k0+k][col0+c]
#pragma unroll
        for (int i = 0; i < 8; i++) {
            int e = t + i * 256;
            int k = e >> 6;
            int c = e & 63;
            Bs[k >> 1][c * 2 + (k & 1)] = W[(size_t)(k0 + k) * N + col0 + c];
        }
        __syncthreads();

#pragma unroll
        for (int dp = 0; dp < TKC / 2; dp++) {
            unsigned long long av[4], bv[4];
#pragma unroll
            for (int i = 0; i < 4; i++)
                av[i] = *(const unsigned long long*)&As[ty * 4 + i][dp * 2];
#pragma unroll
            for (int j = 0; j < 4; j++)
                bv[j] = *(const unsigned long long*)&Bs[dp][(tx * 4 + j) * 2];
#pragma unroll
            for (int i = 0; i < 4; i++)
#pragma unroll
                for (int j = 0; j < 4; j++) fma2(acc[i][j], av[i], bv[j]);
        }
        __syncthreads();
    }

    // Epilogue: bias (+relu) (+knowledge add), coalesced float4 stores
#pragma unroll
    for (int i = 0; i < 4; i++) {
        int row = row0 + ty * 4 + i;
        float4 o;
        float* op = &o.x;
#pragma unroll
        for (int j = 0; j < 4; j++) {
            int col = col0 + tx * 4 + j;
            float v = unpack_sum(acc[i][j]) + bias[col];
            if (RELU) v = fmaxf(v, 0.f);
            if (ADD) v += addsrc[(size_t)row * N + col]; // only used when N==64
            op[j] = v;
        }
        *(float4*)&C[(size_t)row * N + col0 + tx * 4] = o;
    }
}

// ---------------------------------------------------------------------------
// Knowledge branch: one block per batch row b.
//   Gather up to 50 masked kg rows into SMEM (skip mask==0 -> zeros),
//   64x64x64 f32x2 GEMM vs Wkg, then relu(z+bkg)*mask and row-sum -> know[b].
// ---------------------------------------------------------------------------
__global__ __launch_bounds__(256) void knowledge_kernel(
    const float* __restrict__ kg, const int* __restrict__ idx,
    const int* __restrict__ mask, const float* __restrict__ Wkg,
    const float* __restrict__ bkg, float* __restrict__ know)
{
    __shared__ float Gs[64][64];     // gathered rows (k-padded to 64)
    __shared__ float Bs[32][128];    // Wkg paired layout
    __shared__ float maskS[64];
    __shared__ float red[16][64];

    const int b  = blockIdx.x;
    const int t  = threadIdx.x;
    const int tx = t & 15;
    const int ty = t >> 4;

    if (t < 64) maskS[t] = (t < KK) ? (float)mask[b * KK + t] : 0.f;

    // Wkg -> paired SMEM layout
#pragma unroll
    for (int i = 0; i < 16; i++) {
        int e = t + i * 256;
        int k = e >> 6;
        int c = e & 63;
        Bs[k >> 1][c * 2 + (k & 1)] = Wkg[k * 64 + c];
    }

    // Gather: 4 threads per row, 16 floats (4x float4) each.
    {
        int r = t >> 2;
        int q = t & 3;
        bool active = (r < KK) && (mask[b * KK + r] != 0);
        if (active) {
            const float4* src =
                (const float4*)(kg + (size_t)idx[b * KK + r] * 64 + q * 16);
#pragma unroll
            for (int i = 0; i < 4; i++)
                *(float4*)&Gs[r][q * 16 + i * 4] = src[i];
        } else {
            float4 z = make_float4(0.f, 0.f, 0.f, 0.f);
#pragma unroll
            for (int i = 0; i < 4; i++)
                *(float4*)&Gs[r][q * 16 + i * 4] = z;
        }
    }
    __syncthreads();

    unsigned long long acc[4][4];
#pragma unroll
    for (int i = 0; i < 4; i++)
#pragma unroll
        for (int j = 0; j < 4; j++) acc[i][j] = 0ull;

#pragma unroll 8
    for (int dp = 0; dp < 32; dp++) {
        unsigned long long av[4], bv[4];
#pragma unroll
        for (int i = 0; i < 4; i++)
            av[i] = *(const unsigned long long*)&Gs[ty * 4 + i][dp * 2];
#pragma unroll
        for (int j = 0; j < 4; j++)
            bv[j] = *(const unsigned long long*)&Bs[dp][(tx * 4 + j) * 2];
#pragma unroll
        for (int i = 0; i < 4; i++)
#pragma unroll
            for (int j = 0; j < 4; j++) fma2(acc[i][j], av[i], bv[j]);
    }

    // relu(z + bkg) * mask, then partial row-sums per thread
    float cs[4] = {0.f, 0.f, 0.f, 0.f};
#pragma unroll
    for (int i = 0; i < 4; i++) {
        float mr = maskS[ty * 4 + i];
#pragma unroll
        for (int j = 0; j < 4; j++) {
            float v = unpack_sum(acc[i][j]) + bkg[tx * 4 + j];
            v = fmaxf(v, 0.f);
            cs[j] += v * mr;
        }
    }
#pragma unroll
    for (int j = 0; j < 4; j++) red[ty][tx * 4 + j] = cs[j];
    __syncthreads();

    if (t < 64) {
        float s = 0.f;
#pragma unroll
        for (int y = 0; y < 16; y++) s += red[y][t];
        know[b * 64 + t] = s;
    }
}

// ---------------------------------------------------------------------------
// Launch
// ---------------------------------------------------------------------------
extern "C" void kernel_launch(void* const* d_in, const int* in_sizes, int n_in,
                              void* d_out, int out_size)
{
    const float* x   = (const float*)d_in[0];
    const float* kg  = (const float*)d_in[1];
    const int*   idx = (const int*)  d_in[2];
    const int*   msk = (const int*)  d_in[3];
    const float* Wkg = (const float*)d_in[4];
    const float* bkg = (const float*)d_in[5];
    const float* W1a = (const float*)d_in[6];
    const float* b1a = (const float*)d_in[7];
    const float* W1b = (const float*)d_in[8];
    const float* b1b = (const float*)d_in[9];
    const float* W1c = (const float*)d_in[10];
    const float* b1c = (const float*)d_in[11];
    const float* W1d = (const float*)d_in[12];
    const float* b1d = (const float*)d_in[13];
    const float* W2  = (const float*)d_in[14];
    const float* b2  = (const float*)d_in[15];
    float* out = (float*)d_out;

    float *h128a, *h512, *h128b, *h64, *know;
    cudaGetSymbolAddress((void**)&h128a, g_h128a);
    cudaGetSymbolAddress((void**)&h512,  g_h512);
    cudaGetSymbolAddress((void**)&h128b, g_h128b);
    cudaGetSymbolAddress((void**)&h64,   g_h64);
    cudaGetSymbolAddress((void**)&know,  g_know);

    // Knowledge branch
    knowledge_kernel<<<BB, 256>>>(kg, idx, msk, Wkg, bkg, know);

    // MLP chain
    gemm_kernel<512, 128, true,  false><<<dim3(2, BB / TM),  256>>>(x,     W1a, b1a, nullptr, h128a);
    gemm_kernel<128, 512, true,  false><<<dim3(8, BB / TM),  256>>>(h128a, W1b, b1b, nullptr, h512);
    gemm_kernel<512, 128, true,  false><<<dim3(2, BB / TM),  256>>>(h512,  W1c, b1c, nullptr, h128b);
    gemm_kernel<128, 64,  true,  true ><<<dim3(1, BB / TM),  256>>>(h128b, W1d, b1d, know,    h64);

    // Output projection
    gemm_kernel<64, 1024, false, false><<<dim3(16, BB / TM), 256>>>(h64,   W2,  b2,  nullptr, out);
}

// round 5
// speedup vs baseline: 2.1218x; 2.1218x over previous
#include <cuda_runtime.h>
#include <cuda_bf16.h>
#include <stdint.h>

#define BB 8192

// ---------------------------------------------------------------------------
// Device scratch (no cudaMalloc allowed)
// ---------------------------------------------------------------------------
__device__ float g_h1[BB * 128];
__device__ float g_h2[BB * 512];
__device__ float g_h3[BB * 128];
__device__ float g_h4[BB * 64];
__device__ float g_know[BB * 64];

// Pre-split + pre-swizzled weight images ([N][K] K-major, SW128 64x64 tiles)
__device__ __nv_bfloat16 g_Wkg_h[4096],  g_Wkg_l[4096];
__device__ __nv_bfloat16 g_W1a_h[65536], g_W1a_l[65536];
__device__ __nv_bfloat16 g_W1b_h[65536], g_W1b_l[65536];
__device__ __nv_bfloat16 g_W1c_h[65536], g_W1c_l[65536];
__device__ __nv_bfloat16 g_W1d_h[8192],  g_W1d_l[8192];
__device__ __nv_bfloat16 g_W2_h[65536],  g_W2_l[65536];

// ---------------------------------------------------------------------------
// Helpers
// ---------------------------------------------------------------------------
__device__ __forceinline__ uint32_t smem_u32(const void* p) {
    uint32_t a;
    asm("{ .reg .u64 t; cvta.to.shared.u64 t, %1; cvt.u32.u64 %0, t; }"
        : "=r"(a) : "l"(p));
    return a;
}

#define SWZ(x) ((x) ^ (((x) >> 3) & 0x70))

__device__ __forceinline__ uint32_t packbf(float e0, float e1) {
    uint32_t r;
    asm("cvt.rn.bf16x2.f32 %0, %1, %2;" : "=r"(r) : "f"(e1), "f"(e0));
    return r; // low half = e0, high half = e1
}
__device__ __forceinline__ float lof(uint32_t p) { return __uint_as_float(p << 16); }
__device__ __forceinline__ float hif(uint32_t p) { return __uint_as_float(p & 0xffff0000u); }

__device__ __forceinline__ void split8(float4 a, float4 b, uint4& H, uint4& L) {
    uint32_t h0 = packbf(a.x, a.y), h1 = packbf(a.z, a.w);
    uint32_t h2 = packbf(b.x, b.y), h3 = packbf(b.z, b.w);
    L.x = packbf(a.x - lof(h0), a.y - hif(h0));
    L.y = packbf(a.z - lof(h1), a.w - hif(h1));
    L.z = packbf(b.x - lof(h2), b.y - hif(h2));
    L.w = packbf(b.z - lof(h3), b.w - hif(h3));
    H.x = h0; H.y = h1; H.z = h2; H.w = h3;
}

__device__ __forceinline__ void ldsm4(uint32_t* r, uint32_t addr) {
    asm volatile("ldmatrix.sync.aligned.m8n8.x4.shared.b16 {%0,%1,%2,%3}, [%4];"
        : "=r"(r[0]), "=r"(r[1]), "=r"(r[2]), "=r"(r[3]) : "r"(addr));
}

__device__ __forceinline__ void mma16816(float* d, const uint32_t* a,
                                         const uint32_t* b) {
    asm volatile(
        "mma.sync.aligned.m16n8k16.row.col.f32.bf16.bf16.f32 "
        "{%0,%1,%2,%3}, {%4,%5,%6,%7}, {%8,%9}, {%0,%1,%2,%3};"
        : "+f"(d[0]), "+f"(d[1]), "+f"(d[2]), "+f"(d[3])
        : "r"(a[0]), "r"(a[1]), "r"(a[2]), "r"(a[3]), "r"(b[0]), "r"(b[1]));
}

// ---------------------------------------------------------------------------
// Weight prep: split fp32 W[K][N] -> bf16 hi/lo, [N][K] K-major,
// stored as pre-swizzled SW128 64x64-tile images.
// ---------------------------------------------------------------------------
struct PrepArgs {
    const float* src[6];
    __nv_bfloat16 *hi[6], *lo[6];
    int kdim[6], n[6];
    int off[7];
};

__global__ __launch_bounds__(256) void prep_weights(PrepArgs a) {
    int e = blockIdx.x * 256 + threadIdx.x;
#pragma unroll
    for (int sgi = 0; sgi < 6; sgi++) {
        if (e >= a.off[sgi] && e < a.off[sgi + 1]) {
            int le = e - a.off[sgi];
            int N = a.n[sgi], KD = a.kdim[sgi];
            int k = le / N, n = le % N;
            float v = a.src[sgi][le];
            __nv_bfloat16 h = __float2bfloat16_rn(v);
            __nv_bfloat16 l = __float2bfloat16_rn(v - __bfloat162float(h));
            int nt = n >> 6, nl = n & 63, c = k >> 6, kl = k & 63;
            int tile = nt * (KD >> 6) + c;
            uint32_t boff = (uint32_t)nl * 128 + (uint32_t)kl * 2;
            uint32_t so = SWZ(boff);
            int di = tile * 4096 + (int)(so >> 1);
            a.hi[sgi][di] = h;
            a.lo[sgi][di] = l;
        }
    }
}

// ---------------------------------------------------------------------------
// Tensor GEMM (HMMA path): C[8192,NTOT] = act(A @ W + bias)(+addsrc)
// 256 threads, 128x64 tile, warp tile 64x16, split-bf16 3-term mma.
// Dynamic SMEM: Ah@0 (16K), Al@16K, Bh@32K (8K), Bl@40K (8K) = 48K.
// ---------------------------------------------------------------------------
template <int KDIM, int NTOT, bool RELU, bool ADD>
__global__ __launch_bounds__(256, 2) void tgemm(
    const float* __restrict__ A,
    const __nv_bfloat16* __restrict__ Bh_img,
    const __nv_bfloat16* __restrict__ Bl_img,
    const float* __restrict__ bias,
    const float* __restrict__ addsrc,
    float* __restrict__ C)
{
    constexpr int CHUNKS = KDIM / 64;
    extern __shared__ char smem[];
    const uint32_t sb = smem_u32(smem);
    const int t = threadIdx.x, lane = t & 31, wid = t >> 5;
    const int wm = wid & 1, wn = wid >> 1;
    const int row0 = blockIdx.y * 128, nt = blockIdx.x, col0 = nt * 64;

    float acc[4][2][4];
#pragma unroll
    for (int i = 0; i < 4; i++)
#pragma unroll
        for (int j = 0; j < 2; j++)
#pragma unroll
            for (int e = 0; e < 4; e++) acc[i][j][e] = 0.f;

    // Per-thread ldmatrix addresses (within-tile offsets, swizzled)
    const int a_r  = (lane & 15);
    const int a_cb = (lane >> 4) << 4;
    const int b_n  = wn * 16 + ((lane >> 4) << 3) + (lane & 7);
    const int b_cb = ((lane >> 3) & 1) << 4;

#pragma unroll 1
    for (int c = 0; c < CHUNKS; c++) {
        if (c) __syncthreads();
        // A: load fp32 chunk, split to bf16 hi/lo, swizzled STS
        {
            const int row = t >> 1, half = t & 1;
            const float4* ap = (const float4*)(A + (size_t)(row0 + row) * KDIM
                                               + c * 64 + half * 32);
#pragma unroll
            for (int g = 0; g < 4; g++) {
                uint4 H, L;
                split8(ap[2 * g], ap[2 * g + 1], H, L);
                uint32_t off = (uint32_t)row * 128 + half * 64 + g * 16;
                uint32_t so = SWZ(off);
                *(uint4*)(smem + so)         = H;
                *(uint4*)(smem + 16384 + so) = L;
            }
        }
        // B: copy pre-swizzled images
        {
            const uint4* bph = (const uint4*)(Bh_img + ((size_t)nt * CHUNKS + c) * 4096);
            const uint4* bpl = (const uint4*)(Bl_img + ((size_t)nt * CHUNKS + c) * 4096);
#pragma unroll
            for (int i = 0; i < 2; i++) {
                int e = t + i * 256;
                *(uint4*)(smem + 32768 + e * 16) = bph[e];
                *(uint4*)(smem + 40960 + e * 16) = bpl[e];
            }
        }
        __syncthreads();

#pragma unroll
        for (int ks = 0; ks < 4; ks++) {
            uint32_t bh[4], bl[4];
            uint32_t ba = sb + 32768 + SWZ((uint32_t)b_n * 128 + ks * 32 + b_cb);
            ldsm4(bh, ba);
            ldsm4(bl, ba + 8192);
#pragma unroll
            for (int mi = 0; mi < 4; mi++) {
                uint32_t ah[4], al[4];
                int r = wm * 64 + mi * 16 + a_r;
                uint32_t aa = sb + SWZ((uint32_t)r * 128 + ks * 32 + a_cb);
                ldsm4(ah, aa);
                ldsm4(al, aa + 16384);
#pragma unroll
                for (int ni = 0; ni < 2; ni++) {
                    mma16816(acc[mi][ni], ah, bh + 2 * ni);
                    mma16816(acc[mi][ni], al, bh + 2 * ni);
                    mma16816(acc[mi][ni], ah, bl + 2 * ni);
                }
            }
        }
    }

    // Epilogue
    const int g = lane >> 2, q = lane & 3;
#pragma unroll
    for (int mi = 0; mi < 4; mi++) {
        int r0g = row0 + wm * 64 + mi * 16 + g;
#pragma unroll
        for (int ni = 0; ni < 2; ni++) {
            int col = col0 + wn * 16 + ni * 8 + q * 2;
            float b0 = __ldg(bias + col), b1 = __ldg(bias + col + 1);
            float v00 = acc[mi][ni][0] + b0, v01 = acc[mi][ni][1] + b1;
            float v10 = acc[mi][ni][2] + b0, v11 = acc[mi][ni][3] + b1;
            if (RELU) {
                v00 = fmaxf(v00, 0.f); v01 = fmaxf(v01, 0.f);
                v10 = fmaxf(v10, 0.f); v11 = fmaxf(v11, 0.f);
            }
            if (ADD) {
                float2 a0 = *(const float2*)&addsrc[(size_t)r0g * NTOT + col];
                float2 a1 = *(const float2*)&addsrc[(size_t)(r0g + 8) * NTOT + col];
                v00 += a0.x; v01 += a0.y; v10 += a1.x; v11 += a1.y;
            }
            *(float2*)&C[(size_t)r0g * NTOT + col]       = make_float2(v00, v01);
            *(float2*)&C[(size_t)(r0g + 8) * NTOT + col] = make_float2(v10, v11);
        }
    }
}

// ---------------------------------------------------------------------------
// Knowledge branch: 2 batch rows per CTA (64-padded each), 128x64x64 GEMM.
// SMEM: Gh@0 16K, Gl@16K, Bh@32K 8K, Bl@40K 8K, maskf@49152 (512B),
//       idxS@49664 (512B), red@50176 (128x65 f32 = 33280B). Total 83456.
// ---------------------------------------------------------------------------
__global__ __launch_bounds__(256, 2) void tknow(
    const float* __restrict__ kg, const int* __restrict__ idx,
    const int* __restrict__ mask,
    const __nv_bfloat16* __restrict__ Wh, const __nv_bfloat16* __restrict__ Wl,
    const float* __restrict__ bkg, float* __restrict__ know)
{
    extern __shared__ char smem[];
    const uint32_t sb = smem_u32(smem);
    const int t = threadIdx.x, lane = t & 31, wid = t >> 5;
    const int wm = wid & 1, wn = wid >> 1;
    const int b0 = blockIdx.x * 2;

    float* maskS = (float*)(smem + 49152);
    int*   idxS  = (int*)(smem + 49664);
    float* red   = (float*)(smem + 50176);

    if (t < 128) {
        int bb = b0 + (t >> 6), k = t & 63;
        int m = 0, ix = -1;
        if (k < 50) {
            m = mask[bb * 50 + k];
            if (m) ix = idx[bb * 50 + k];
        }
        maskS[t] = (float)m;
        idxS[t] = ix;
    }
    __syncthreads();

    // Gather + split (2 threads per gathered row)
    {
        const int row = t >> 1, half = t & 1;
        int ix = idxS[row];
        if (ix >= 0) {
            const float4* src = (const float4*)(kg + (size_t)ix * 64 + half * 32);
#pragma unroll
            for (int g = 0; g < 4; g++) {
                uint4 H, L;
                split8(src[2 * g], src[2 * g + 1], H, L);
                uint32_t off = (uint32_t)row * 128 + half * 64 + g * 16;
                uint32_t so = SWZ(off);
                *(uint4*)(smem + so)         = H;
                *(uint4*)(smem + 16384 + so) = L;
            }
        } else {
            uint4 Z = make_uint4(0, 0, 0, 0);
#pragma unroll
            for (int g = 0; g < 4; g++) {
                uint32_t off = (uint32_t)row * 128 + half * 64 + g * 16;
                uint32_t so = SWZ(off);
                *(uint4*)(smem + so)         = Z;
                *(uint4*)(smem + 16384 + so) = Z;
            }
        }
        // Wkg images (single tile each)
#pragma unroll
        for (int i = 0; i < 2; i++) {
            int e = t + i * 256;
            *(uint4*)(smem + 32768 + e * 16) = ((const uint4*)Wh)[e];
            *(uint4*)(smem + 40960 + e * 16) = ((const uint4*)Wl)[e];
        }
    }
    __syncthreads();

    float acc[4][2][4];
#pragma unroll
    for (int i = 0; i < 4; i++)
#pragma unroll
        for (int j = 0; j < 2; j++)
#pragma unroll
            for (int e = 0; e < 4; e++) acc[i][j][e] = 0.f;

    const int a_r  = (lane & 15);
    const int a_cb = (lane >> 4) << 4;
    const int b_n  = wn * 16 + ((lane >> 4) << 3) + (lane & 7);
    const int b_cb = ((lane >> 3) & 1) << 4;

#pragma unroll
    for (int ks = 0; ks < 4; ks++) {
        uint32_t bh[4], bl[4];
        uint32_t ba = sb + 32768 + SWZ((uint32_t)b_n * 128 + ks * 32 + b_cb);
        ldsm4(bh, ba);
        ldsm4(bl, ba + 8192);
#pragma unroll
        for (int mi = 0; mi < 4; mi++) {
            uint32_t ah[4], al[4];
            int r = wm * 64 + mi * 16 + a_r;
            uint32_t aa = sb + SWZ((uint32_t)r * 128 + ks * 32 + a_cb);
            ldsm4(ah, aa);
            ldsm4(al, aa + 16384);
#pragma unroll
            for (int ni = 0; ni < 2; ni++) {
                mma16816(acc[mi][ni], ah, bh + 2 * ni);
                mma16816(acc[mi][ni], al, bh + 2 * ni);
                mma16816(acc[mi][ni], ah, bl + 2 * ni);
            }
        }
    }

    // Epilogue: relu(z+bkg)*mask -> red -> column sums per batch row
    const int g = lane >> 2, q = lane & 3;
#pragma unroll
    for (int mi = 0; mi < 4; mi++) {
        int rr = wm * 64 + mi * 16 + g;
        float m0 = maskS[rr], m1 = maskS[rr + 8];
#pragma unroll
        for (int ni = 0; ni < 2; ni++) {
            int col = wn * 16 + ni * 8 + q * 2;
            float b0 = __ldg(bkg + col), b1 = __ldg(bkg + col + 1);
            red[rr * 65 + col]           = fmaxf(acc[mi][ni][0] + b0, 0.f) * m0;
            red[rr * 65 + col + 1]       = fmaxf(acc[mi][ni][1] + b1, 0.f) * m0;
            red[(rr + 8) * 65 + col]     = fmaxf(acc[mi][ni][2] + b0, 0.f) * m1;
            red[(rr + 8) * 65 + col + 1] = fmaxf(acc[mi][ni][3] + b1, 0.f) * m1;
        }
    }
    __syncthreads();

    if (t < 128) {
        int h = t >> 6, c2 = t & 63;
        float s = 0.f;
#pragma unroll
        for (int r = 0; r < 64; r++) s += red[(h * 64 + r) * 65 + c2];
        know[(size_t)(b0 + h) * 64 + c2] = s;
    }
}

// ---------------------------------------------------------------------------
// Launch
// ---------------------------------------------------------------------------
extern "C" void kernel_launch(void* const* d_in, const int* in_sizes, int n_in,
                              void* d_out, int out_size)
{
    const float* x   = (const float*)d_in[0];
    const float* kg  = (const float*)d_in[1];
    const int*   idx = (const int*)  d_in[2];
    const int*   msk = (const int*)  d_in[3];
    const float* Wkg = (const float*)d_in[4];
    const float* bkg = (const float*)d_in[5];
    const float* W1a = (const float*)d_in[6];
    const float* b1a = (const float*)d_in[7];
    const float* W1b = (const float*)d_in[8];
    const float* b1b = (const float*)d_in[9];
    const float* W1c = (const float*)d_in[10];
    const float* b1c = (const float*)d_in[11];
    const float* W1d = (const float*)d_in[12];
    const float* b1d = (const float*)d_in[13];
    const float* W2  = (const float*)d_in[14];
    const float* b2  = (const float*)d_in[15];
    float* out = (float*)d_out;

    float *h1, *h2, *h3, *h4, *know;
    cudaGetSymbolAddress((void**)&h1, g_h1);
    cudaGetSymbolAddress((void**)&h2, g_h2);
    cudaGetSymbolAddress((void**)&h3, g_h3);
    cudaGetSymbolAddress((void**)&h4, g_h4);
    cudaGetSymbolAddress((void**)&know, g_know);

    __nv_bfloat16 *wkgh, *wkgl, *w1ah, *w1al, *w1bh, *w1bl, *w1ch, *w1cl,
                  *w1dh, *w1dl, *w2h, *w2l;
    cudaGetSymbolAddress((void**)&wkgh, g_Wkg_h); cudaGetSymbolAddress((void**)&wkgl, g_Wkg_l);
    cudaGetSymbolAddress((void**)&w1ah, g_W1a_h); cudaGetSymbolAddress((void**)&w1al, g_W1a_l);
    cudaGetSymbolAddress((void**)&w1bh, g_W1b_h); cudaGetSymbolAddress((void**)&w1bl, g_W1b_l);
    cudaGetSymbolAddress((void**)&w1ch, g_W1c_h); cudaGetSymbolAddress((void**)&w1cl, g_W1c_l);
    cudaGetSymbolAddress((void**)&w1dh, g_W1d_h); cudaGetSymbolAddress((void**)&w1dl, g_W1d_l);
    cudaGetSymbolAddress((void**)&w2h,  g_W2_h);  cudaGetSymbolAddress((void**)&w2l,  g_W2_l);

    const int GEMM_SMEM = 49152;
    const int KNOW_SMEM = 83456;
    cudaFuncSetAttribute(tgemm<512, 128, true,  false>, cudaFuncAttributeMaxDynamicSharedMemorySize, GEMM_SMEM);
    cudaFuncSetAttribute(tgemm<128, 512, true,  false>, cudaFuncAttributeMaxDynamicSharedMemorySize, GEMM_SMEM);
    cudaFuncSetAttribute(tgemm<128, 64,  true,  true >, cudaFuncAttributeMaxDynamicSharedMemorySize, GEMM_SMEM);
    cudaFuncSetAttribute(tgemm<64, 1024, false, false>, cudaFuncAttributeMaxDynamicSharedMemorySize, GEMM_SMEM);
    cudaFuncSetAttribute(tknow, cudaFuncAttributeMaxDynamicSharedMemorySize, KNOW_SMEM);

    // Weight prep (one kernel, all 6 weights)
    PrepArgs pa;
    pa.src[0] = Wkg; pa.hi[0] = wkgh; pa.lo[0] = wkgl; pa.kdim[0] = 64;  pa.n[0] = 64;
    pa.src[1] = W1a; pa.hi[1] = w1ah; pa.lo[1] = w1al; pa.kdim[1] = 512; pa.n[1] = 128;
    pa.src[2] = W1b; pa.hi[2] = w1bh; pa.lo[2] = w1bl; pa.kdim[2] = 128; pa.n[2] = 512;
    pa.src[3] = W1c; pa.hi[3] = w1ch; pa.lo[3] = w1cl; pa.kdim[3] = 512; pa.n[3] = 128;
    pa.src[4] = W1d; pa.hi[4] = w1dh; pa.lo[4] = w1dl; pa.kdim[4] = 128; pa.n[4] = 64;
    pa.src[5] = W2;  pa.hi[5] = w2h;  pa.lo[5] = w2l;  pa.kdim[5] = 64;  pa.n[5] = 1024;
    pa.off[0] = 0;      pa.off[1] = 4096;   pa.off[2] = 69632;  pa.off[3] = 135168;
    pa.off[4] = 200704; pa.off[5] = 208896; pa.off[6] = 274432;
    prep_weights<<<1072, 256>>>(pa);

    // Knowledge branch
    tknow<<<BB / 2, 256, KNOW_SMEM>>>(kg, idx, msk, wkgh, wkgl, bkg, know);

    // MLP chain
    tgemm<512, 128, true,  false><<<dim3(2, 64),  256, GEMM_SMEM>>>(x,  w1ah, w1al, b1a, nullptr, h1);
    tgemm<128, 512, true,  false><<<dim3(8, 64),  256, GEMM_SMEM>>>(h1, w1bh, w1bl, b1b, nullptr, h2);
    tgemm<512, 128, true,  false><<<dim3(2, 64),  256, GEMM_SMEM>>>(h2, w1ch, w1cl, b1c, nullptr, h3);
    tgemm<128, 64,  true,  true ><<<dim3(1, 64),  256, GEMM_SMEM>>>(h3, w1dh, w1dl, b1d, know,    h4);
    tgemm<64, 1024, false, false><<<dim3(16, 64), 256, GEMM_SMEM>>>(h4, w2h,  w2l,  b2,  nullptr, out);
}